// round 3
// baseline (speedup 1.0000x reference)
#include <cuda_runtime.h>
#include <cstdint>

#define SEQ    2048
#define BATCH  4096
#define IN     4
#define HID    3
#define UNR    8                   // timesteps per group
#define NGRP   (SEQ / UNR)         // 256
#define XS     4                   // x smem stages (cp.async pipeline depth)

typedef unsigned long long u64;

// ---- packed f32x2 helpers (Blackwell) ----
__device__ __forceinline__ u64 pack2(float lo, float hi) {
    u64 r; asm("mov.b64 %0, {%1, %2};" : "=l"(r) : "f"(lo), "f"(hi)); return r;
}
__device__ __forceinline__ u64 bcast2(float v) {
    u64 r; asm("mov.b64 %0, {%1, %1};" : "=l"(r) : "f"(v)); return r;
}
__device__ __forceinline__ u64 fma2(u64 a, u64 b, u64 c) {
    u64 d; asm("fma.rn.f32x2 %0, %1, %2, %3;" : "=l"(d) : "l"(a), "l"(b), "l"(c)); return d;
}
__device__ __forceinline__ float2 unpack2(u64 v) {
    float2 r; asm("mov.b64 {%0, %1}, %2;" : "=f"(r.x), "=f"(r.y) : "l"(v)); return r;
}

// ---- cp.async ----
__device__ __forceinline__ void cp_async16(void* smem_dst, const void* gmem_src) {
    uint32_t s;
    asm("{ .reg .u64 t; cvta.to.shared.u64 t, %1; cvt.u32.u64 %0, t; }"
        : "=r"(s) : "l"(smem_dst));
    asm volatile("cp.async.ca.shared.global [%0], [%1], 16;"
                 :: "r"(s), "l"(gmem_src) : "memory");
}
__device__ __forceinline__ void cp_async_commit() {
    asm volatile("cp.async.commit_group;" ::: "memory");
}
template <int N>
__device__ __forceinline__ void cp_async_wait() {
    asm volatile("cp.async.wait_group %0;" :: "n"(N) : "memory");
}

__global__ void __launch_bounds__(64, 1)
rnn_relu_kernel(const float* __restrict__ x,      // [SEQ, BATCH, 4]
                const float* __restrict__ h0,     // [1, BATCH, 3]
                const float* __restrict__ W_ih,   // [3, 4]
                const float* __restrict__ W_hh,   // [3, 3]
                const float* __restrict__ b_ih,   // [3]
                const float* __restrict__ b_hh,   // [3]
                float* __restrict__ out)
{
    // Warp 0: compute (one chain per lane). Warp 1: cp.async producer + gmem storer.
    __shared__ float4 xs[XS][UNR][32];          // 16 KB input stage
    __shared__ float  hout[2][UNR][32 * HID];   // 6 KB output ping-pong (96 floats/row)

    const int lane = threadIdx.x & 31;
    const int warp = threadIdx.x >> 5;
    const int b0   = blockIdx.x * 32;
    const int b    = b0 + lane;

    const float4* __restrict__ xv = (const float4*)x;  // [SEQ][BATCH]
    float* __restrict__ outs  = out;
    float* __restrict__ hlast = out + (size_t)SEQ * BATCH * HID;

    if (warp == 0) {
        // ---------------- compute warp ----------------
        // Pre-pack weights: hidden units (0,1) as f32x2 pairs, unit 2 scalar.
        u64 wih01[IN], whh01[HID];
        float wih2[IN], whh2[HID];
#pragma unroll
        for (int i = 0; i < IN; i++) {
            wih01[i] = pack2(W_ih[0 * IN + i], W_ih[1 * IN + i]);
            wih2[i]  = W_ih[2 * IN + i];
        }
#pragma unroll
        for (int i = 0; i < HID; i++) {
            whh01[i] = pack2(W_hh[0 * HID + i], W_hh[1 * HID + i]);
            whh2[i]  = W_hh[2 * HID + i];
        }
        const u64   bias01 = pack2(b_ih[0] + b_hh[0], b_ih[1] + b_hh[1]);
        const float bias2  = b_ih[2] + b_hh[2];

        float h0r = h0[b * HID + 0];
        float h1r = h0[b * HID + 1];
        float h2r = h0[b * HID + 2];

        __syncthreads();  // sync #0: producer primed xs[0..2], xs[0] complete

        for (int g = 0; g < NGRP; g++) {
            const int xstage = g & (XS - 1);
            const int hslot  = g & 1;
#pragma unroll
            for (int k = 0; k < UNR; k++) {
                const float4 xt = xs[xstage][k][lane];

                // Input projection (off the serial chain): units (0,1) packed.
                u64 p01 = fma2(wih01[0], bcast2(xt.x), bias01);
                p01 = fma2(wih01[1], bcast2(xt.y), p01);
                p01 = fma2(wih01[2], bcast2(xt.z), p01);
                p01 = fma2(wih01[3], bcast2(xt.w), p01);
                float p2 = fmaf(wih2[0], xt.x, bias2);
                p2 = fmaf(wih2[1], xt.y, p2);
                p2 = fmaf(wih2[2], xt.z, p2);
                p2 = fmaf(wih2[3], xt.w, p2);

                // Recurrent update.
                u64 a01 = fma2(whh01[0], bcast2(h0r), p01);
                a01 = fma2(whh01[1], bcast2(h1r), a01);
                a01 = fma2(whh01[2], bcast2(h2r), a01);
                float a2 = fmaf(whh2[0], h0r, p2);
                a2 = fmaf(whh2[1], h1r, a2);
                a2 = fmaf(whh2[2], h2r, a2);

                const float2 a = unpack2(a01);
                h0r = fmaxf(a.x, 0.0f);
                h1r = fmaxf(a.y, 0.0f);
                h2r = fmaxf(a2, 0.0f);

                hout[hslot][k][lane * HID + 0] = h0r;
                hout[hslot][k][lane * HID + 1] = h1r;
                hout[hslot][k][lane * HID + 2] = h2r;
            }
            __syncthreads();  // group g done; storer may drain hslot
        }

        hlast[b * HID + 0] = h0r;
        hlast[b * HID + 1] = h1r;
        hlast[b * HID + 2] = h2r;
    } else {
        // ---------------- producer / storer warp ----------------
        // Prime x pipeline: groups 0,1,2.
#pragma unroll
        for (int s = 0; s < XS - 1; s++) {
#pragma unroll
            for (int k = 0; k < UNR; k++)
                cp_async16(&xs[s][k][lane], &xv[(size_t)(s * UNR + k) * BATCH + b]);
            cp_async_commit();
        }
        cp_async_wait<XS - 2>();  // xs[0] complete
        __syncthreads();          // sync #0

        for (int g = 0; g < NGRP; g++) {
            // Issue loads for group g+3 into stage (g+3)%4.
            const int gl = g + XS - 1;
            if (gl < NGRP) {
                const int s = gl & (XS - 1);
#pragma unroll
                for (int k = 0; k < UNR; k++)
                    cp_async16(&xs[s][k][lane],
                               &xv[(size_t)(gl * UNR + k) * BATCH + b]);
            }
            cp_async_commit();        // uniform group accounting
            cp_async_wait<XS - 2>();  // groups <= g+1 complete

            // Drain outputs of group g-1 (compute finished it at sync g-1).
            if (g > 0 && lane < 24) {
                const int gd = g - 1;
                const float* src = &hout[gd & 1][0][0];
                const size_t tbase = (size_t)gd * UNR;
#pragma unroll
                for (int k = 0; k < UNR; k++) {
                    const float4 v = *(const float4*)(src + k * 32 * HID + lane * 4);
                    *(float4*)(outs + ((tbase + k) * BATCH + b0) * HID + lane * 4) = v;
                }
            }
            __syncthreads();  // sync g
        }

        // Drain the final group (NGRP-1).
        if (lane < 24) {
            const int gd = NGRP - 1;
            const float* src = &hout[gd & 1][0][0];
            const size_t tbase = (size_t)gd * UNR;
#pragma unroll
            for (int k = 0; k < UNR; k++) {
                const float4 v = *(const float4*)(src + k * 32 * HID + lane * 4);
                *(float4*)(outs + ((tbase + k) * BATCH + b0) * HID + lane * 4) = v;
            }
        }
    }
}

extern "C" void kernel_launch(void* const* d_in, const int* in_sizes, int n_in,
                              void* d_out, int out_size)
{
    const float* x    = (const float*)d_in[0];
    const float* h0   = (const float*)d_in[1];
    const float* W_ih = (const float*)d_in[2];
    const float* W_hh = (const float*)d_in[3];
    const float* b_ih = (const float*)d_in[4];
    const float* b_hh = (const float*)d_in[5];
    float* out = (float*)d_out;

    rnn_relu_kernel<<<BATCH / 32, 64>>>(x, h0, W_ih, W_hh, b_ih, b_hh, out);
}